// round 11
// baseline (speedup 1.0000x reference)
#include <cuda_runtime.h>
#include <cuda_pipeline.h>
#include <math.h>

// Problem dims
#define BSz 4
#define Nn  256
#define DXx 256
#define DEe 64
#define DYy 64
#define NHh 8
#define DFf 32

// Output layout: newX (4,256,256) | newE (4,256,256,64) | newY (4,64)
#define OFF_NEWX 0
#define OFF_NEWE 262144
#define OFF_NEWY 17039360

typedef unsigned long long ull;

// packed f32x2 helpers (sm_100+: fma.rn.f32x2 — not emitted by ptxas from C++)
__device__ __forceinline__ ull fma2(ull a, ull b, ull c) {
    ull d;
    asm("fma.rn.f32x2 %0, %1, %2, %3;" : "=l"(d) : "l"(a), "l"(b), "l"(c));
    return d;
}
__device__ __forceinline__ ull pack2(float lo, float hi) {
    ull d; asm("mov.b64 %0, {%1, %2};" : "=l"(d) : "f"(lo), "f"(hi)); return d;
}
__device__ __forceinline__ ull dup2(float v) {
    ull d; asm("mov.b64 %0, {%1, %1};" : "=l"(d) : "f"(v)); return d;
}
__device__ __forceinline__ float hsum2(ull v) {
    float lo, hi; asm("mov.b64 {%0, %1}, %2;" : "=f"(lo), "=f"(hi) : "l"(v));
    return lo + hi;
}

// ---------------- scratch (no runtime allocs allowed) ----------------
__device__ __align__(16) float g_q[BSz*Nn*DXx];    // masked & pre-scaled by 1/sqrt(DF)
__device__ __align__(16) float g_k[BSz*Nn*DXx];    // masked
__device__ __align__(16) float g_v[BSz*Nn*DXx];    // masked
__device__ __align__(16) float g_yx1[BSz*DXx];
__device__ __align__(16) float g_yx2[BSz*DXx];
__device__ __align__(16) float g_W2 [BSz*DXx*DEe]; // (ye2+1)*We_out
__device__ __align__(16) float g_cst[BSz*DEe];     // sum_f ye1*We_out + be_out
__device__ __align__(16) float g_xpool[BSz*4*DXx]; // mean|min|max|std over i
__device__ __align__(16) float g_ep[BSz*64*4*DEe]; // partial e-pool (64 chunks of 4 rows)

// ---------------- q,k,v projections ----------------
__global__ void __launch_bounds__(256) k_qkv(
    const float* __restrict__ x, const float* __restrict__ Wq,
    const float* __restrict__ Wk, const float* __restrict__ Wv,
    const float* __restrict__ mask)
{
    __shared__ __align__(16) float xs[DXx];
    int b = blockIdx.x >> 8, i = blockIdx.x & 255;
    int f = threadIdx.x;
    xs[f] = x[(b*Nn + i)*DXx + f];
    __syncthreads();
    float q = 0.f, k = 0.f, v = 0.f;
#pragma unroll 1
    for (int d = 0; d < DXx; d += 4) {
        float4 x4 = *reinterpret_cast<const float4*>(&xs[d]);
        const float* wq = Wq + d*DXx + f;
        const float* wk = Wk + d*DXx + f;
        const float* wv = Wv + d*DXx + f;
        q = fmaf(x4.x, wq[0], q); q = fmaf(x4.y, wq[DXx], q);
        q = fmaf(x4.z, wq[2*DXx], q); q = fmaf(x4.w, wq[3*DXx], q);
        k = fmaf(x4.x, wk[0], k); k = fmaf(x4.y, wk[DXx], k);
        k = fmaf(x4.z, wk[2*DXx], k); k = fmaf(x4.w, wk[3*DXx], k);
        v = fmaf(x4.x, wv[0], v); v = fmaf(x4.y, wv[DXx], v);
        v = fmaf(x4.z, wv[2*DXx], v); v = fmaf(x4.w, wv[3*DXx], v);
    }
    float mi = mask[b*Nn + i];
    int o = (b*Nn + i)*DXx + f;
    g_q[o] = q * mi * 0.17677669529663688f;  // 1/sqrt(32)
    g_k[o] = k * mi;
    g_v[o] = v * mi;
}

// ---------------- y-side projections + W2 + const ----------------
__global__ void __launch_bounds__(256) k_ypre(
    const float* __restrict__ y,
    const float* __restrict__ Wye_add, const float* __restrict__ Wye_mul,
    const float* __restrict__ Wyx_add, const float* __restrict__ Wyx_mul,
    const float* __restrict__ We_out,  const float* __restrict__ be_out)
{
    __shared__ float ye1s[BSz*DXx];
    int f = threadIdx.x;
    for (int b = 0; b < BSz; ++b) {
        float a = 0.f, m = 0.f, xa = 0.f, xm = 0.f;
#pragma unroll 1
        for (int d = 0; d < DYy; ++d) {
            float yv = y[b*DYy + d];
            a  = fmaf(yv, Wye_add[d*DXx + f], a);
            m  = fmaf(yv, Wye_mul[d*DXx + f], m);
            xa = fmaf(yv, Wyx_add[d*DXx + f], xa);
            xm = fmaf(yv, Wyx_mul[d*DXx + f], xm);
        }
        g_yx1[b*DXx + f] = xa;
        g_yx2[b*DXx + f] = xm;
        ye1s[b*DXx + f] = a;
        float coef = m + 1.0f;
#pragma unroll
        for (int c = 0; c < DEe; c += 4) {
            float4 w = *reinterpret_cast<const float4*>(&We_out[f*DEe + c]);
            float4 o;
            o.x = coef*w.x; o.y = coef*w.y; o.z = coef*w.z; o.w = coef*w.w;
            *reinterpret_cast<float4*>(&g_W2[(b*DXx + f)*DEe + c]) = o;
        }
    }
    __syncthreads();
    int b = f >> 6, c = f & 63;
    float s = be_out[c];
#pragma unroll 1
    for (int ff = 0; ff < DXx; ++ff)
        s = fmaf(ye1s[b*DXx + ff], We_out[ff*DEe + c], s);
    g_cst[b*DEe + c] = s;
}

// ---------------- x pool over i ----------------
__global__ void __launch_bounds__(256) k_xpool(const float* __restrict__ x)
{
    int b = blockIdx.x, f = threadIdx.x;
    float s = 0.f, ss = 0.f, mn = 1e30f, mx = -1e30f;
#pragma unroll 1
    for (int i = 0; i < Nn; ++i) {
        float v = x[(b*Nn + i)*DXx + f];
        s += v; ss = fmaf(v, v, ss);
        mn = fminf(mn, v); mx = fmaxf(mx, v);
    }
    float M = (float)Nn;
    float mean = s / M;
    float var = (ss - s*s/M) / (M - 1.0f);
    float* dst = &g_xpool[b*4*DXx];
    dst[0*DXx + f] = mean;
    dst[1*DXx + f] = mn;
    dst[2*DXx + f] = mx;
    dst[3*DXx + f] = sqrtf(fmaxf(var, 0.f));
}

// ---------------- e pool stage 1: 64 chunks of 4 i-rows, float4 loads ----------------
__global__ void __launch_bounds__(256) k_epool1(const float* __restrict__ e)
{
    int b = blockIdx.y, ch = blockIdx.x;     // ch in [0,64)
    int t = threadIdx.x;
    int qg = t & 15;                          // 4-column group: cols 4qg..4qg+3
    int jp = t >> 4;                          // j phase 0..15
    float4 s  = make_float4(0.f,0.f,0.f,0.f);
    float4 ss = make_float4(0.f,0.f,0.f,0.f);
    float4 mn = make_float4(1e30f,1e30f,1e30f,1e30f);
    float4 mx = make_float4(-1e30f,-1e30f,-1e30f,-1e30f);
    int i0 = ch * 4;
#pragma unroll 1
    for (int i = i0; i < i0 + 4; ++i) {
        const float4* __restrict__ base =
            reinterpret_cast<const float4*>(e) + (size_t)((b*Nn + i)*Nn)*16;
#pragma unroll 4
        for (int j = jp; j < Nn; j += 16) {
            float4 v = base[j*16 + qg];
            s.x += v.x; s.y += v.y; s.z += v.z; s.w += v.w;
            ss.x = fmaf(v.x,v.x,ss.x); ss.y = fmaf(v.y,v.y,ss.y);
            ss.z = fmaf(v.z,v.z,ss.z); ss.w = fmaf(v.w,v.w,ss.w);
            mn.x = fminf(mn.x,v.x); mn.y = fminf(mn.y,v.y);
            mn.z = fminf(mn.z,v.z); mn.w = fminf(mn.w,v.w);
            mx.x = fmaxf(mx.x,v.x); mx.y = fmaxf(mx.y,v.y);
            mx.z = fmaxf(mx.z,v.z); mx.w = fmaxf(mx.w,v.w);
        }
    }
    __shared__ float sh[16][4][64];           // [jp][stat][col]
    int c0 = qg*4;
    sh[jp][0][c0+0]=s.x;  sh[jp][0][c0+1]=s.y;  sh[jp][0][c0+2]=s.z;  sh[jp][0][c0+3]=s.w;
    sh[jp][1][c0+0]=ss.x; sh[jp][1][c0+1]=ss.y; sh[jp][1][c0+2]=ss.z; sh[jp][1][c0+3]=ss.w;
    sh[jp][2][c0+0]=mn.x; sh[jp][2][c0+1]=mn.y; sh[jp][2][c0+2]=mn.z; sh[jp][2][c0+3]=mn.w;
    sh[jp][3][c0+0]=mx.x; sh[jp][3][c0+1]=mx.y; sh[jp][3][c0+2]=mx.z; sh[jp][3][c0+3]=mx.w;
    __syncthreads();
    int col = t & 63, st = t >> 6;            // st uniform per warp-pair
    float r = sh[0][st][col];
    if (st < 2) {
#pragma unroll
        for (int p = 1; p < 16; ++p) r += sh[p][st][col];
    } else if (st == 2) {
#pragma unroll
        for (int p = 1; p < 16; ++p) r = fminf(r, sh[p][st][col]);
    } else {
#pragma unroll
        for (int p = 1; p < 16; ++p) r = fmaxf(r, sh[p][st][col]);
    }
    g_ep[(((b*64 + ch)*4) + st)*64 + col] = r;
}

// ---------------- newY (pools combine + small matmuls) ----------------
__global__ void __launch_bounds__(256) k_final(
    const float* __restrict__ y,   const float* __restrict__ Wyy,
    const float* __restrict__ Wxy, const float* __restrict__ bxy,
    const float* __restrict__ Wey, const float* __restrict__ bey,
    const float* __restrict__ Wy_out, const float* __restrict__ by_out,
    float* __restrict__ out_newY)
{
    __shared__ float ep[BSz][4*DEe];
    __shared__ float tot[BSz][DYy];
    int t = threadIdx.x;
    int b = t >> 6, dy = t & 63;
    {   // combine e-pool partials
        int c = dy;
        float s = 0.f, ss = 0.f, mn = 1e30f, mx = -1e30f;
#pragma unroll 1
        for (int ch = 0; ch < 64; ++ch) {
            const float* p = &g_ep[((b*64 + ch)*4)*64];
            s += p[0*64 + c]; ss += p[1*64 + c];
            mn = fminf(mn, p[2*64 + c]); mx = fmaxf(mx, p[3*64 + c]);
        }
        float M = (float)(Nn*Nn);
        ep[b][0*DEe + c] = s / M;
        ep[b][1*DEe + c] = mn;
        ep[b][2*DEe + c] = mx;
        ep[b][3*DEe + c] = sqrtf(fmaxf((ss - s*s/M)/(M - 1.0f), 0.f));
    }
    __syncthreads();
    float xy = bxy[dy];
#pragma unroll 1
    for (int p = 0; p < 4*DXx; ++p)
        xy = fmaf(g_xpool[b*4*DXx + p], Wxy[p*DYy + dy], xy);
    float ey = bey[dy];
#pragma unroll 1
    for (int p = 0; p < 4*DEe; ++p)
        ey = fmaf(ep[b][p], Wey[p*DYy + dy], ey);
    float yy = 0.f;
#pragma unroll 1
    for (int d = 0; d < DYy; ++d)
        yy = fmaf(y[b*DYy + d], Wyy[d*DYy + dy], yy);
    tot[b][dy] = xy + ey + yy;
    __syncthreads();
    float o = by_out[dy];
#pragma unroll 1
    for (int d = 0; d < DYy; ++d)
        o = fmaf(tot[b][d], Wy_out[d*DYy + dy], o);
    out_newY[b*DYy + dy] = o;
}

// ---------------- main fused kernel: e1/e2, Y, newE, softmax-attn, newX ----------------
// dynamic smem layout (floats):
//   W2sh  [256*64]      = 16384   (per-batch modulated We_out, staged once)
//   Ysh   [16][256]     =  4096
//   e_sh  [2][16*64]    =  2048   (double-buffered e chunk, cp.async)
//   msh   [256]         =   256
#define SM_W2   0
#define SM_Y    16384
#define SM_E    (16384 + 4096)
#define SM_M    (16384 + 4096 + 2048)
#define SM_TOT  (16384 + 4096 + 2048 + 256)

__global__ void __launch_bounds__(256, 2) k_main(
    const float* __restrict__ e, const float* __restrict__ node_mask,
    const float* __restrict__ We_mul, const float* __restrict__ We_add,
    const float* __restrict__ Wx_out, const float* __restrict__ bx_out,
    float* __restrict__ out)
{
    extern __shared__ __align__(16) float sm[];
    float* __restrict__ W2sh = sm + SM_W2;
    float* __restrict__ Ysh  = sm + SM_Y;    // [16][256]
    float* __restrict__ e_db = sm + SM_E;    // [2][1024]
    float* __restrict__ msh  = sm + SM_M;

    int b = blockIdx.x >> 8, i = blockIdx.x & 255;
    int f = threadIdx.x;
    msh[f] = node_mask[b*Nn + f];
    // stage W2 (16384 floats) once
    {
        const float4* src = reinterpret_cast<const float4*>(g_W2 + b*DXx*DEe);
        float4* dst = reinterpret_cast<float4*>(W2sh);
#pragma unroll
        for (int t = 0; t < 16; ++t)
            dst[f + t*256] = src[f + t*256];
    }
    float mi = node_mask[b*Nn + i];
    float qf = g_q[(b*Nn + i)*DXx + f];

    // online softmax state (per feature f, over j)
    float m = -1e30f, ssum = 0.f, acc = 0.f;

    const float* __restrict__ erow = e + ((b*Nn + i)*Nn)*DEe;
    // projection thread mapping: one (jt, 4-wide c) tile per thread
    int jt_p = f >> 4;
    int c0   = (f & 15) * 4;
    float4 cst4 = *reinterpret_cast<const float4*>(&g_cst[b*DEe + c0]);
    float* __restrict__ outE = out + OFF_NEWE + (size_t)(b*Nn + i)*Nn*DEe;

    // prefetch e chunk 0
    __pipeline_memcpy_async(e_db + f*4, erow + f*4, 16);
    __pipeline_commit();

    for (int jc = 0; jc < 16; ++jc) {
        int j0 = jc * 16;
        if (jc + 1 < 16) {   // prefetch next chunk into alternate buffer
            __pipeline_memcpy_async(e_db + ((jc+1)&1)*1024 + f*4,
                                    erow + (j0+16)*DEe + f*4, 16);
            __pipeline_commit();
            __pipeline_wait_prior(1);
        } else {
            __pipeline_wait_prior(0);
        }
        __syncthreads();     // current buffer visible to all; Ysh free for reuse
        const float* __restrict__ e_sh = e_db + (jc&1)*1024;  // [16][64]

        // e1/e2 GEMM in packed f32x2: 16 jt rows x 2 packed accumulators
        ull e1acc[16], e2acc[16];
#pragma unroll
        for (int jt = 0; jt < 16; ++jt) { e1acc[jt] = 0ULL; e2acc[jt] = 0ULL; }
#pragma unroll 1
        for (int kk = 0; kk < 64; kk += 4) {
            const float* wmp = We_mul + kk*DXx + f;
            const float* wap = We_add + kk*DXx + f;
            ull wm01 = pack2(wmp[0],      wmp[DXx]);
            ull wm23 = pack2(wmp[2*DXx],  wmp[3*DXx]);
            ull wa01 = pack2(wap[0],      wap[DXx]);
            ull wa23 = pack2(wap[2*DXx],  wap[3*DXx]);
#pragma unroll
            for (int jt = 0; jt < 16; ++jt) {
                ulonglong2 ev = *reinterpret_cast<const ulonglong2*>(&e_sh[jt*64 + kk]);
                e1acc[jt] = fma2(ev.x, wm01, fma2(ev.y, wm23, e1acc[jt]));
                e2acc[jt] = fma2(ev.x, wa01, fma2(ev.y, wa23, e2acc[jt]));
            }
        }

        // pass 1: horizontal-reduce accs, form Y, stage it, stash (vj, masked-Y),
        // track chunk max — ONE corr exp per chunk.
        float cm = -1e30f;
        float vst[16], yst[16];
#pragma unroll
        for (int jt = 0; jt < 16; ++jt) {
            int j = j0 + jt;
            float e1 = hsum2(e1acc[jt]);
            float e2 = hsum2(e2acc[jt]);
            float mj = msh[j];
            float em = mi * mj;
            float kj = g_k[(b*Nn + j)*DXx + f];
            float vj = g_v[(b*Nn + j)*DXx + f];
            // Y = (q*k/sqrt(df)) * (e1*em + 1) + e2*em   (q pre-scaled)
            float yv = fmaf(qf*kj, fmaf(e1, em, 1.0f), e2*em);
            Ysh[jt*DXx + f] = yv;
            float ym = (mj > 0.f) ? yv : -1e9f;
            cm = fmaxf(cm, ym);
            vst[jt] = vj;
            yst[jt] = ym;
        }
        float nm = fmaxf(m, cm);
        float corr = __expf(m - nm);
        ssum *= corr; acc *= corr; m = nm;
        __syncthreads();

        // pass 2: one exp per element; interleaves with projection FFMA stream
#pragma unroll
        for (int jt = 0; jt < 16; ++jt) {
            float p = __expf(yst[jt] - nm);
            ssum += p;
            acc = fmaf(p, vst[jt], acc);
        }

        // newE projection: Ytile(16x256) @ W2sh(256x64) + const, *em
        // packed over c: a01 = (c0,c0+1), a23 = (c0+2,c0+3)
        ull a01 = 0ULL, a23 = 0ULL;
        const float* __restrict__ yrow = Ysh + jt_p*DXx;
        const float* __restrict__ w2p = W2sh + c0;
#pragma unroll 4
        for (int ff = 0; ff < DXx; ff += 4) {
            float4 y4 = *reinterpret_cast<const float4*>(&yrow[ff]);
            ulonglong2 w0 = *reinterpret_cast<const ulonglong2*>(&w2p[(ff+0)*DEe]);
            ulonglong2 w1 = *reinterpret_cast<const ulonglong2*>(&w2p[(ff+1)*DEe]);
            ulonglong2 w2 = *reinterpret_cast<const ulonglong2*>(&w2p[(ff+2)*DEe]);
            ulonglong2 w3 = *reinterpret_cast<const ulonglong2*>(&w2p[(ff+3)*DEe]);
            ull yx = dup2(y4.x), yy = dup2(y4.y), yz = dup2(y4.z), yw = dup2(y4.w);
            a01 = fma2(yx, w0.x, a01); a23 = fma2(yx, w0.y, a23);
            a01 = fma2(yy, w1.x, a01); a23 = fma2(yy, w1.y, a23);
            a01 = fma2(yz, w2.x, a01); a23 = fma2(yz, w2.y, a23);
            a01 = fma2(yw, w3.x, a01); a23 = fma2(yw, w3.y, a23);
        }
        {
            int j = j0 + jt_p;
            float em = mi * msh[j];
            float a0, a1, a2, a3;
            asm("mov.b64 {%0, %1}, %2;" : "=f"(a0), "=f"(a1) : "l"(a01));
            asm("mov.b64 {%0, %1}, %2;" : "=f"(a2), "=f"(a3) : "l"(a23));
            float4 r;
            r.x = (a0 + cst4.x) * em;
            r.y = (a1 + cst4.y) * em;
            r.z = (a2 + cst4.z) * em;
            r.w = (a3 + cst4.w) * em;
            *reinterpret_cast<float4*>(&outE[(size_t)j*DEe + c0]) = r;
        }
    }

    // attention finalize + yx modulation
    float wsum = acc / ssum;
    float tval = fmaf(g_yx2[b*DXx + f] + 1.0f, wsum, g_yx1[b*DXx + f]);
    __syncthreads();
    float* tsh = e_db;       // reuse
    tsh[f] = tval;
    __syncthreads();

    // newX = t @ Wx_out + bx_out, * mask_i
    float o = bx_out[f];
#pragma unroll 1
    for (int d = 0; d < DXx; d += 4) {
        float4 t4 = *reinterpret_cast<const float4*>(&tsh[d]);
        const float* w = Wx_out + d*DXx + f;
        o = fmaf(t4.x, w[0], o);
        o = fmaf(t4.y, w[DXx], o);
        o = fmaf(t4.z, w[2*DXx], o);
        o = fmaf(t4.w, w[3*DXx], o);
    }
    out[OFF_NEWX + (b*Nn + i)*DXx + f] = o * mi;
}

// ---------------- launch ----------------
extern "C" void kernel_launch(void* const* d_in, const int* in_sizes, int n_in,
                              void* d_out, int out_size)
{
    const float* x        = (const float*)d_in[0];
    const float* e        = (const float*)d_in[1];
    const float* y        = (const float*)d_in[2];
    const float* node_mask= (const float*)d_in[3];
    const float* Wq       = (const float*)d_in[4];
    const float* Wk       = (const float*)d_in[5];
    const float* Wv       = (const float*)d_in[6];
    const float* We_mul   = (const float*)d_in[7];
    const float* We_add   = (const float*)d_in[8];
    const float* Wye_add  = (const float*)d_in[9];
    const float* Wye_mul  = (const float*)d_in[10];
    const float* Wyx_add  = (const float*)d_in[11];
    const float* Wyx_mul  = (const float*)d_in[12];
    const float* Wyy      = (const float*)d_in[13];
    const float* Wxy      = (const float*)d_in[14];
    const float* bxy      = (const float*)d_in[15];
    const float* Wey      = (const float*)d_in[16];
    const float* bey      = (const float*)d_in[17];
    const float* We_out   = (const float*)d_in[18];
    const float* be_out   = (const float*)d_in[19];
    const float* Wx_out   = (const float*)d_in[20];
    const float* bx_out   = (const float*)d_in[21];
    const float* Wy_out   = (const float*)d_in[22];
    const float* by_out   = (const float*)d_in[23];
    float* out = (float*)d_out;

    static int smem_set = -1;
    const int kMainSmem = SM_TOT * (int)sizeof(float);   // 91136 B
    if (smem_set < 0) {
        cudaFuncSetAttribute(k_main, cudaFuncAttributeMaxDynamicSharedMemorySize,
                             kMainSmem);
        smem_set = 1;
    }

    k_qkv  <<<BSz*Nn, 256>>>(x, Wq, Wk, Wv, node_mask);
    k_ypre <<<1, 256>>>(y, Wye_add, Wye_mul, Wyx_add, Wyx_mul, We_out, be_out);
    k_xpool<<<BSz, 256>>>(x);
    k_epool1<<<dim3(64, BSz), 256>>>(e);
    k_final<<<1, 256>>>(y, Wyy, Wxy, bxy, Wey, bey, Wy_out, by_out, out + OFF_NEWY);
    k_main <<<BSz*Nn, 256, kMainSmem>>>(e, node_mask, We_mul, We_add, Wx_out, bx_out, out);
}

// round 12
// speedup vs baseline: 1.5510x; 1.5510x over previous
#include <cuda_runtime.h>
#include <cuda_pipeline.h>
#include <math.h>

// Problem dims
#define BSz 4
#define Nn  256
#define DXx 256
#define DEe 64
#define DYy 64
#define NHh 8
#define DFf 32

// Output layout: newX (4,256,256) | newE (4,256,256,64) | newY (4,64)
#define OFF_NEWX 0
#define OFF_NEWE 262144
#define OFF_NEWY 17039360

typedef unsigned long long ull;

// packed f32x2 helpers (sm_100+: fma.rn.f32x2 — not emitted by ptxas from C++)
__device__ __forceinline__ ull fma2(ull a, ull b, ull c) {
    ull d;
    asm("fma.rn.f32x2 %0, %1, %2, %3;" : "=l"(d) : "l"(a), "l"(b), "l"(c));
    return d;
}
__device__ __forceinline__ ull pack2(float lo, float hi) {
    ull d; asm("mov.b64 %0, {%1, %2};" : "=l"(d) : "f"(lo), "f"(hi)); return d;
}
__device__ __forceinline__ ull dup2(float v) {
    ull d; asm("mov.b64 %0, {%1, %1};" : "=l"(d) : "f"(v)); return d;
}
__device__ __forceinline__ float hsum2(ull v) {
    float lo, hi; asm("mov.b64 {%0, %1}, %2;" : "=f"(lo), "=f"(hi) : "l"(v));
    return lo + hi;
}

// ---------------- scratch (no runtime allocs allowed) ----------------
__device__ __align__(16) float g_q[BSz*Nn*DXx];    // masked & pre-scaled by 1/sqrt(DF)
__device__ __align__(16) float g_k[BSz*Nn*DXx];    // masked
__device__ __align__(16) float g_v[BSz*Nn*DXx];    // masked
__device__ __align__(16) float g_yx1[BSz*DXx];
__device__ __align__(16) float g_yx2[BSz*DXx];
__device__ __align__(16) float g_W2 [BSz*DXx*DEe]; // (ye2+1)*We_out
__device__ __align__(16) float g_cst[BSz*DEe];     // sum_f ye1*We_out + be_out
__device__ __align__(16) float g_xpool[BSz*4*DXx]; // mean|min|max|std over i
__device__ __align__(16) float g_ep[BSz*64*4*DEe]; // partial e-pool (64 chunks of 4 rows)

// ---------------- q,k,v projections ----------------
__global__ void __launch_bounds__(256) k_qkv(
    const float* __restrict__ x, const float* __restrict__ Wq,
    const float* __restrict__ Wk, const float* __restrict__ Wv,
    const float* __restrict__ mask)
{
    __shared__ __align__(16) float xs[DXx];
    int b = blockIdx.x >> 8, i = blockIdx.x & 255;
    int f = threadIdx.x;
    xs[f] = x[(b*Nn + i)*DXx + f];
    __syncthreads();
    float q = 0.f, k = 0.f, v = 0.f;
#pragma unroll 2
    for (int d = 0; d < DXx; d += 4) {
        float4 x4 = *reinterpret_cast<const float4*>(&xs[d]);
        const float* wq = Wq + d*DXx + f;
        const float* wk = Wk + d*DXx + f;
        const float* wv = Wv + d*DXx + f;
        q = fmaf(x4.x, wq[0], q); q = fmaf(x4.y, wq[DXx], q);
        q = fmaf(x4.z, wq[2*DXx], q); q = fmaf(x4.w, wq[3*DXx], q);
        k = fmaf(x4.x, wk[0], k); k = fmaf(x4.y, wk[DXx], k);
        k = fmaf(x4.z, wk[2*DXx], k); k = fmaf(x4.w, wk[3*DXx], k);
        v = fmaf(x4.x, wv[0], v); v = fmaf(x4.y, wv[DXx], v);
        v = fmaf(x4.z, wv[2*DXx], v); v = fmaf(x4.w, wv[3*DXx], v);
    }
    float mi = mask[b*Nn + i];
    int o = (b*Nn + i)*DXx + f;
    g_q[o] = q * mi * 0.17677669529663688f;  // 1/sqrt(32)
    g_k[o] = k * mi;
    g_v[o] = v * mi;
}

// ---------------- y-side projections + W2 + const (one CTA per batch) ----------------
__global__ void __launch_bounds__(256) k_ypre(
    const float* __restrict__ y,
    const float* __restrict__ Wye_add, const float* __restrict__ Wye_mul,
    const float* __restrict__ Wyx_add, const float* __restrict__ Wyx_mul,
    const float* __restrict__ We_out,  const float* __restrict__ be_out)
{
    __shared__ float ye1s[DXx];
    __shared__ float ysh[DYy];
    int b = blockIdx.x;
    int f = threadIdx.x;
    if (f < DYy) ysh[f] = y[b*DYy + f];
    __syncthreads();
    float a = 0.f, m = 0.f, xa = 0.f, xm = 0.f;
#pragma unroll 4
    for (int d = 0; d < DYy; ++d) {
        float yv = ysh[d];
        a  = fmaf(yv, Wye_add[d*DXx + f], a);
        m  = fmaf(yv, Wye_mul[d*DXx + f], m);
        xa = fmaf(yv, Wyx_add[d*DXx + f], xa);
        xm = fmaf(yv, Wyx_mul[d*DXx + f], xm);
    }
    g_yx1[b*DXx + f] = xa;
    g_yx2[b*DXx + f] = xm;
    ye1s[f] = a;
    float coef = m + 1.0f;
#pragma unroll
    for (int c = 0; c < DEe; c += 4) {
        float4 w = *reinterpret_cast<const float4*>(&We_out[f*DEe + c]);
        float4 o;
        o.x = coef*w.x; o.y = coef*w.y; o.z = coef*w.z; o.w = coef*w.w;
        *reinterpret_cast<float4*>(&g_W2[(b*DXx + f)*DEe + c]) = o;
    }
    __syncthreads();
    if (f < DEe) {
        int c = f;
        float s = be_out[c];
#pragma unroll 4
        for (int ff = 0; ff < DXx; ++ff)
            s = fmaf(ye1s[ff], We_out[ff*DEe + c], s);
        g_cst[b*DEe + c] = s;
    }
}

// ---------------- x pool over i (4-wide MLP) ----------------
__global__ void __launch_bounds__(256) k_xpool(const float* __restrict__ x)
{
    int b = blockIdx.x, f = threadIdx.x;
    float s = 0.f, ss = 0.f, mn = 1e30f, mx = -1e30f;
#pragma unroll 1
    for (int i = 0; i < Nn; i += 4) {
        float v0 = x[(b*Nn + i+0)*DXx + f];
        float v1 = x[(b*Nn + i+1)*DXx + f];
        float v2 = x[(b*Nn + i+2)*DXx + f];
        float v3 = x[(b*Nn + i+3)*DXx + f];
        s += v0 + v1 + v2 + v3;
        ss = fmaf(v0,v0,ss); ss = fmaf(v1,v1,ss);
        ss = fmaf(v2,v2,ss); ss = fmaf(v3,v3,ss);
        mn = fminf(mn, fminf(fminf(v0,v1), fminf(v2,v3)));
        mx = fmaxf(mx, fmaxf(fmaxf(v0,v1), fmaxf(v2,v3)));
    }
    float M = (float)Nn;
    float mean = s / M;
    float var = (ss - s*s/M) / (M - 1.0f);
    float* dst = &g_xpool[b*4*DXx];
    dst[0*DXx + f] = mean;
    dst[1*DXx + f] = mn;
    dst[2*DXx + f] = mx;
    dst[3*DXx + f] = sqrtf(fmaxf(var, 0.f));
}

// ---------------- e pool stage 1: 64 chunks of 4 i-rows, float4 loads ----------------
__global__ void __launch_bounds__(256) k_epool1(const float* __restrict__ e)
{
    int b = blockIdx.y, ch = blockIdx.x;     // ch in [0,64)
    int t = threadIdx.x;
    int qg = t & 15;                          // 4-column group: cols 4qg..4qg+3
    int jp = t >> 4;                          // j phase 0..15
    float4 s  = make_float4(0.f,0.f,0.f,0.f);
    float4 ss = make_float4(0.f,0.f,0.f,0.f);
    float4 mn = make_float4(1e30f,1e30f,1e30f,1e30f);
    float4 mx = make_float4(-1e30f,-1e30f,-1e30f,-1e30f);
    int i0 = ch * 4;
#pragma unroll 1
    for (int i = i0; i < i0 + 4; ++i) {
        const float4* __restrict__ base =
            reinterpret_cast<const float4*>(e) + (size_t)((b*Nn + i)*Nn)*16;
#pragma unroll 4
        for (int j = jp; j < Nn; j += 16) {
            float4 v = base[j*16 + qg];
            s.x += v.x; s.y += v.y; s.z += v.z; s.w += v.w;
            ss.x = fmaf(v.x,v.x,ss.x); ss.y = fmaf(v.y,v.y,ss.y);
            ss.z = fmaf(v.z,v.z,ss.z); ss.w = fmaf(v.w,v.w,ss.w);
            mn.x = fminf(mn.x,v.x); mn.y = fminf(mn.y,v.y);
            mn.z = fminf(mn.z,v.z); mn.w = fminf(mn.w,v.w);
            mx.x = fmaxf(mx.x,v.x); mx.y = fmaxf(mx.y,v.y);
            mx.z = fmaxf(mx.z,v.z); mx.w = fmaxf(mx.w,v.w);
        }
    }
    __shared__ float sh[16][4][64];           // [jp][stat][col]
    int c0 = qg*4;
    sh[jp][0][c0+0]=s.x;  sh[jp][0][c0+1]=s.y;  sh[jp][0][c0+2]=s.z;  sh[jp][0][c0+3]=s.w;
    sh[jp][1][c0+0]=ss.x; sh[jp][1][c0+1]=ss.y; sh[jp][1][c0+2]=ss.z; sh[jp][1][c0+3]=ss.w;
    sh[jp][2][c0+0]=mn.x; sh[jp][2][c0+1]=mn.y; sh[jp][2][c0+2]=mn.z; sh[jp][2][c0+3]=mn.w;
    sh[jp][3][c0+0]=mx.x; sh[jp][3][c0+1]=mx.y; sh[jp][3][c0+2]=mx.z; sh[jp][3][c0+3]=mx.w;
    __syncthreads();
    int col = t & 63, st = t >> 6;            // st uniform per warp-pair
    float r = sh[0][st][col];
    if (st < 2) {
#pragma unroll
        for (int p = 1; p < 16; ++p) r += sh[p][st][col];
    } else if (st == 2) {
#pragma unroll
        for (int p = 1; p < 16; ++p) r = fminf(r, sh[p][st][col]);
    } else {
#pragma unroll
        for (int p = 1; p < 16; ++p) r = fmaxf(r, sh[p][st][col]);
    }
    g_ep[(((b*64 + ch)*4) + st)*64 + col] = r;
}

// ---------------- newY (pools combine + small matmuls) ----------------
__global__ void __launch_bounds__(256) k_final(
    const float* __restrict__ y,   const float* __restrict__ Wyy,
    const float* __restrict__ Wxy, const float* __restrict__ bxy,
    const float* __restrict__ Wey, const float* __restrict__ bey,
    const float* __restrict__ Wy_out, const float* __restrict__ by_out,
    float* __restrict__ out_newY)
{
    __shared__ float ep[BSz][4*DEe];
    __shared__ float tot[BSz][DYy];
    int t = threadIdx.x;
    int b = t >> 6, dy = t & 63;
    {   // combine e-pool partials
        int c = dy;
        float s = 0.f, ss = 0.f, mn = 1e30f, mx = -1e30f;
#pragma unroll 2
        for (int ch = 0; ch < 64; ++ch) {
            const float* p = &g_ep[((b*64 + ch)*4)*64];
            s += p[0*64 + c]; ss += p[1*64 + c];
            mn = fminf(mn, p[2*64 + c]); mx = fmaxf(mx, p[3*64 + c]);
        }
        float M = (float)(Nn*Nn);
        ep[b][0*DEe + c] = s / M;
        ep[b][1*DEe + c] = mn;
        ep[b][2*DEe + c] = mx;
        ep[b][3*DEe + c] = sqrtf(fmaxf((ss - s*s/M)/(M - 1.0f), 0.f));
    }
    __syncthreads();
    float xy = bxy[dy];
#pragma unroll 4
    for (int p = 0; p < 4*DXx; ++p)
        xy = fmaf(g_xpool[b*4*DXx + p], Wxy[p*DYy + dy], xy);
    float ey = bey[dy];
#pragma unroll 4
    for (int p = 0; p < 4*DEe; ++p)
        ey = fmaf(ep[b][p], Wey[p*DYy + dy], ey);
    float yy = 0.f;
#pragma unroll 4
    for (int d = 0; d < DYy; ++d)
        yy = fmaf(y[b*DYy + d], Wyy[d*DYy + dy], yy);
    tot[b][dy] = xy + ey + yy;
    __syncthreads();
    float o = by_out[dy];
#pragma unroll 4
    for (int d = 0; d < DYy; ++d)
        o = fmaf(tot[b][d], Wy_out[d*DYy + dy], o);
    out_newY[b*DYy + dy] = o;
}

// ---------------- main fused kernel: e1/e2, Y, newE, softmax-attn, newX ----------------
// dynamic smem layout (floats):
//   Ysh  [16][256]      =  4096
//   e_db [2][16*64]     =  2048   (double-buffered e chunk, cp.async)
//   k_db [2][16*256]    =  8192   (double-buffered k chunk, cp.async)
//   v_db [2][16*256]    =  8192   (double-buffered v chunk, cp.async)
//   msh  [256]          =   256
#define SM_Y    0
#define SM_E    4096
#define SM_K    (4096 + 2048)
#define SM_V    (4096 + 2048 + 8192)
#define SM_M    (4096 + 2048 + 8192 + 8192)
#define SM_TOT  (4096 + 2048 + 8192 + 8192 + 256)

__global__ void __launch_bounds__(256, 2) k_main(
    const float* __restrict__ e, const float* __restrict__ node_mask,
    const float* __restrict__ We_mul, const float* __restrict__ We_add,
    const float* __restrict__ Wx_out, const float* __restrict__ bx_out,
    float* __restrict__ out)
{
    extern __shared__ __align__(16) float sm[];
    float* __restrict__ Ysh  = sm + SM_Y;    // [16][256]
    float* __restrict__ e_db = sm + SM_E;    // [2][1024]
    float* __restrict__ k_db = sm + SM_K;    // [2][4096]
    float* __restrict__ v_db = sm + SM_V;    // [2][4096]
    float* __restrict__ msh  = sm + SM_M;

    int b = blockIdx.x >> 8, i = blockIdx.x & 255;
    int f = threadIdx.x;
    msh[f] = node_mask[b*Nn + f];
    float mi = node_mask[b*Nn + i];
    float qf = g_q[(b*Nn + i)*DXx + f];

    // online softmax state (per feature f, over j)
    float m = -1e30f, ssum = 0.f, acc = 0.f;

    const float* __restrict__ erow = e + ((b*Nn + i)*Nn)*DEe;
    const float* __restrict__ krow = g_k + (size_t)b*Nn*DXx;
    const float* __restrict__ vrow = g_v + (size_t)b*Nn*DXx;
    // projection thread mapping: one (jt, 4-wide c) tile per thread
    int jt_p = f >> 4;
    int c0   = (f & 15) * 4;
    float4 cst4 = *reinterpret_cast<const float4*>(&g_cst[b*DEe + c0]);
    const float* __restrict__ W2b = g_W2 + b*DXx*DEe;
    float* __restrict__ outE = out + OFF_NEWE + (size_t)(b*Nn + i)*Nn*DEe;

    // prologue: prefetch e/k/v for chunk 0 (each chunk: e=4KB, k=16KB, v=16KB)
    __pipeline_memcpy_async(e_db + f*4, erow + f*4, 16);
#pragma unroll
    for (int t = 0; t < 4; ++t) {
        __pipeline_memcpy_async(k_db + f*4 + t*1024, krow + f*4 + t*1024, 16);
        __pipeline_memcpy_async(v_db + f*4 + t*1024, vrow + f*4 + t*1024, 16);
    }
    __pipeline_commit();

    for (int jc = 0; jc < 16; ++jc) {
        int j0 = jc * 16;
        if (jc + 1 < 16) {   // prefetch next chunk into alternate buffers
            int nb = (jc+1) & 1;
            int jn = j0 + 16;
            __pipeline_memcpy_async(e_db + nb*1024 + f*4, erow + jn*DEe + f*4, 16);
#pragma unroll
            for (int t = 0; t < 4; ++t) {
                __pipeline_memcpy_async(k_db + nb*4096 + f*4 + t*1024,
                                        krow + jn*DXx + f*4 + t*1024, 16);
                __pipeline_memcpy_async(v_db + nb*4096 + f*4 + t*1024,
                                        vrow + jn*DXx + f*4 + t*1024, 16);
            }
            __pipeline_commit();
            __pipeline_wait_prior(1);
        } else {
            __pipeline_wait_prior(0);
        }
        __syncthreads();     // current buffers visible; Ysh free for reuse
        int buf = jc & 1;
        const float* __restrict__ e_sh = e_db + buf*1024;   // [16][64]
        const float* __restrict__ k_sh = k_db + buf*4096;   // [16][256]
        const float* __restrict__ v_sh = v_db + buf*4096;   // [16][256]

        // e1/e2 GEMM in packed f32x2, software-pipelined weight loads
        ull e1acc[16], e2acc[16];
#pragma unroll
        for (int jt = 0; jt < 16; ++jt) { e1acc[jt] = 0ULL; e2acc[jt] = 0ULL; }
        float nm0, nm1, nm2, nm3, na0, na1, na2, na3;
        {
            const float* wmp = We_mul + f;
            const float* wap = We_add + f;
            nm0 = wmp[0];      nm1 = wmp[DXx];
            nm2 = wmp[2*DXx];  nm3 = wmp[3*DXx];
            na0 = wap[0];      na1 = wap[DXx];
            na2 = wap[2*DXx];  na3 = wap[3*DXx];
        }
#pragma unroll 1
        for (int kk = 0; kk < 64; kk += 4) {
            ull wm01 = pack2(nm0, nm1);
            ull wm23 = pack2(nm2, nm3);
            ull wa01 = pack2(na0, na1);
            ull wa23 = pack2(na2, na3);
            if (kk + 4 < 64) {   // prefetch next iteration's weights
                const float* wmp = We_mul + (kk+4)*DXx + f;
                const float* wap = We_add + (kk+4)*DXx + f;
                nm0 = wmp[0];      nm1 = wmp[DXx];
                nm2 = wmp[2*DXx];  nm3 = wmp[3*DXx];
                na0 = wap[0];      na1 = wap[DXx];
                na2 = wap[2*DXx];  na3 = wap[3*DXx];
            }
#pragma unroll
            for (int jt = 0; jt < 16; ++jt) {
                ulonglong2 ev = *reinterpret_cast<const ulonglong2*>(&e_sh[jt*64 + kk]);
                e1acc[jt] = fma2(ev.x, wm01, fma2(ev.y, wm23, e1acc[jt]));
                e2acc[jt] = fma2(ev.x, wa01, fma2(ev.y, wa23, e2acc[jt]));
            }
        }

        // pass 1: reduce accs, form Y, stage it, stash (vj, masked-Y),
        // track chunk max — ONE corr exp per chunk. k/v from smem (no LDG).
        float cm = -1e30f;
        float vst[16], yst[16];
#pragma unroll
        for (int jt = 0; jt < 16; ++jt) {
            int j = j0 + jt;
            float e1 = hsum2(e1acc[jt]);
            float e2 = hsum2(e2acc[jt]);
            float mj = msh[j];
            float em = mi * mj;
            float kj = k_sh[jt*DXx + f];
            float vj = v_sh[jt*DXx + f];
            // Y = (q*k/sqrt(df)) * (e1*em + 1) + e2*em   (q pre-scaled)
            float yv = fmaf(qf*kj, fmaf(e1, em, 1.0f), e2*em);
            Ysh[jt*DXx + f] = yv;
            float ym = (mj > 0.f) ? yv : -1e9f;
            cm = fmaxf(cm, ym);
            vst[jt] = vj;
            yst[jt] = ym;
        }
        float nm = fmaxf(m, cm);
        float corr = __expf(m - nm);
        ssum *= corr; acc *= corr; m = nm;
        __syncthreads();

        // pass 2: one exp per element; interleaves with projection FFMA stream
#pragma unroll
        for (int jt = 0; jt < 16; ++jt) {
            float p = __expf(yst[jt] - nm);
            ssum += p;
            acc = fmaf(p, vst[jt], acc);
        }

        // newE projection: Ytile(16x256) @ W2(256x64) + const, *em
        // packed over c: a01 = (c0,c0+1), a23 = (c0+2,c0+3); W2 hits L1
        ull a01 = 0ULL, a23 = 0ULL;
        const float* __restrict__ yrow = Ysh + jt_p*DXx;
        const float* __restrict__ w2p = W2b + c0;
#pragma unroll 4
        for (int ff = 0; ff < DXx; ff += 4) {
            float4 y4 = *reinterpret_cast<const float4*>(&yrow[ff]);
            ulonglong2 w0 = *reinterpret_cast<const ulonglong2*>(&w2p[(ff+0)*DEe]);
            ulonglong2 w1 = *reinterpret_cast<const ulonglong2*>(&w2p[(ff+1)*DEe]);
            ulonglong2 w2 = *reinterpret_cast<const ulonglong2*>(&w2p[(ff+2)*DEe]);
            ulonglong2 w3 = *reinterpret_cast<const ulonglong2*>(&w2p[(ff+3)*DEe]);
            ull yx = dup2(y4.x), yy = dup2(y4.y), yz = dup2(y4.z), yw = dup2(y4.w);
            a01 = fma2(yx, w0.x, a01); a23 = fma2(yx, w0.y, a23);
            a01 = fma2(yy, w1.x, a01); a23 = fma2(yy, w1.y, a23);
            a01 = fma2(yz, w2.x, a01); a23 = fma2(yz, w2.y, a23);
            a01 = fma2(yw, w3.x, a01); a23 = fma2(yw, w3.y, a23);
        }
        {
            int j = j0 + jt_p;
            float em = mi * msh[j];
            float a0, a1, a2, a3;
            asm("mov.b64 {%0, %1}, %2;" : "=f"(a0), "=f"(a1) : "l"(a01));
            asm("mov.b64 {%0, %1}, %2;" : "=f"(a2), "=f"(a3) : "l"(a23));
            float4 r;
            r.x = (a0 + cst4.x) * em;
            r.y = (a1 + cst4.y) * em;
            r.z = (a2 + cst4.z) * em;
            r.w = (a3 + cst4.w) * em;
            *reinterpret_cast<float4*>(&outE[(size_t)j*DEe + c0]) = r;
        }
    }

    // attention finalize + yx modulation
    float wsum = acc / ssum;
    float tval = fmaf(g_yx2[b*DXx + f] + 1.0f, wsum, g_yx1[b*DXx + f]);
    __syncthreads();
    float* tsh = Ysh;        // reuse
    tsh[f] = tval;
    __syncthreads();

    // newX = t @ Wx_out + bx_out, * mask_i
    float o = bx_out[f];
#pragma unroll 2
    for (int d = 0; d < DXx; d += 4) {
        float4 t4 = *reinterpret_cast<const float4*>(&tsh[d]);
        const float* w = Wx_out + d*DXx + f;
        o = fmaf(t4.x, w[0], o);
        o = fmaf(t4.y, w[DXx], o);
        o = fmaf(t4.z, w[2*DXx], o);
        o = fmaf(t4.w, w[3*DXx], o);
    }
    out[OFF_NEWX + (b*Nn + i)*DXx + f] = o * mi;
}

// ---------------- launch ----------------
extern "C" void kernel_launch(void* const* d_in, const int* in_sizes, int n_in,
                              void* d_out, int out_size)
{
    const float* x        = (const float*)d_in[0];
    const float* e        = (const float*)d_in[1];
    const float* y        = (const float*)d_in[2];
    const float* node_mask= (const float*)d_in[3];
    const float* Wq       = (const float*)d_in[4];
    const float* Wk       = (const float*)d_in[5];
    const float* Wv       = (const float*)d_in[6];
    const float* We_mul   = (const float*)d_in[7];
    const float* We_add   = (const float*)d_in[8];
    const float* Wye_add  = (const float*)d_in[9];
    const float* Wye_mul  = (const float*)d_in[10];
    const float* Wyx_add  = (const float*)d_in[11];
    const float* Wyx_mul  = (const float*)d_in[12];
    const float* Wyy      = (const float*)d_in[13];
    const float* Wxy      = (const float*)d_in[14];
    const float* bxy      = (const float*)d_in[15];
    const float* Wey      = (const float*)d_in[16];
    const float* bey      = (const float*)d_in[17];
    const float* We_out   = (const float*)d_in[18];
    const float* be_out   = (const float*)d_in[19];
    const float* Wx_out   = (const float*)d_in[20];
    const float* bx_out   = (const float*)d_in[21];
    const float* Wy_out   = (const float*)d_in[22];
    const float* by_out   = (const float*)d_in[23];
    float* out = (float*)d_out;

    static int smem_set = -1;
    const int kMainSmem = SM_TOT * (int)sizeof(float);   // 91136 B
    if (smem_set < 0) {
        cudaFuncSetAttribute(k_main, cudaFuncAttributeMaxDynamicSharedMemorySize,
                             kMainSmem);
        smem_set = 1;
    }

    // order chosen so ncu (-s 5 -c 1 skip window) lands on k_main next round
    k_qkv  <<<BSz*Nn, 256>>>(x, Wq, Wk, Wv, node_mask);
    k_ypre <<<BSz, 256>>>(y, Wye_add, Wye_mul, Wyx_add, Wyx_mul, We_out, be_out);
    k_xpool<<<BSz, 256>>>(x);
    k_main <<<BSz*Nn, 256, kMainSmem>>>(e, node_mask, We_mul, We_add, Wx_out, bx_out, out);
    k_epool1<<<dim3(64, BSz), 256>>>(e);
    k_final<<<1, 256>>>(y, Wyy, Wxy, bxy, Wey, bey, Wy_out, by_out, out + OFF_NEWY);
}